// round 1
// baseline (speedup 1.0000x reference)
#include <cuda_runtime.h>
#include <math.h>

#define BB 8
#define CC 64
#define LL 2048
#define MM 1024
#define GG 4
#define CPG 16
#define HH 8
#define EE 8
#define EPSV 1e-5f

// ---------------- scratch (device globals; no allocation allowed) ----------------
__device__ float g_xat[BB*CC*LL];   // x_atten
__device__ float g_qp [BB*CC*LL];   // q_ (k-conv of x_atten)
__device__ float g_xa [BB*CC*MM];   // down-conv output (pre-BN)
__device__ float g_v  [BB*CC*MM];   // v
__device__ float g_v1 [BB*CC*MM];   // v1
__device__ float g_out[BB*CC*LL];   // attention output
__device__ float g_xs [BB*CC*LL];   // out + x_atten
__device__ float g_xs2[BB*CC*LL];   // conv-out + xs (pre final BN)
__device__ float g_s1d[CC];         // down BN sum
__device__ float g_s2d[CC];         // down BN sumsq
__device__ float g_s1f[CC];         // final BN sum
__device__ float g_s2f[CC];         // final BN sumsq

// ---------------- K0: zero stat accumulators ----------------
__global__ void k0_init() {
    int t = threadIdx.x;
    if (t < CC) { g_s1d[t] = 0.f; g_s2d[t] = 0.f; g_s1f[t] = 0.f; g_s2f[t] = 0.f; }
}

// ---------------- K1: q conv -> sigmoid gate -> x_atten -> q_ conv ----------------
// pointwise grouped convs; each thread owns one (b,l) column, per group independent.
__global__ void __launch_bounds__(128) k1_gate(const float* __restrict__ x,
                                               const float* __restrict__ qw,
                                               const float* __restrict__ kw) {
    __shared__ float qws[CC*CPG], kws[CC*CPG];
    for (int i = threadIdx.x; i < CC*CPG; i += blockDim.x) { qws[i] = qw[i]; kws[i] = kw[i]; }
    __syncthreads();
    int gl = blockIdx.x * blockDim.x + threadIdx.x;   // over B*L
    int b = gl >> 11, l = gl & (LL-1);
    size_t base = (size_t)b*CC*LL + l;
    for (int g = 0; g < GG; g++) {
        float xv[CPG], xa[CPG];
        #pragma unroll
        for (int i = 0; i < CPG; i++) xv[i] = x[base + (size_t)(g*CPG+i)*LL];
        #pragma unroll
        for (int c = 0; c < CPG; c++) {
            float s = 0.f;
            #pragma unroll
            for (int i = 0; i < CPG; i++) s = fmaf(qws[(g*CPG+c)*CPG+i], xv[i], s);
            xa[c] = xv[c] / (1.f + __expf(-s));
        }
        #pragma unroll
        for (int i = 0; i < CPG; i++) g_xat[base + (size_t)(g*CPG+i)*LL] = xa[i];
        #pragma unroll
        for (int c = 0; c < CPG; c++) {
            float s = 0.f;
            #pragma unroll
            for (int i = 0; i < CPG; i++) s = fmaf(kws[(g*CPG+c)*CPG+i], xa[i], s);
            g_qp[base + (size_t)(g*CPG+c)*LL] = s;
        }
    }
}

// ---------------- K2: odd/even shuffle + down conv (K=3, groups=2) + BN stats ----------------
#define TM2 64
__global__ void __launch_bounds__(256) k2_down(const float* __restrict__ dw) {
    __shared__ float xt[CC][2*TM2 + 4];   // l-range [2*m0-2, 2*m0+130)
    int t = threadIdx.x;
    int m0 = blockIdx.x * TM2, b = blockIdx.y;
    int l0 = 2*m0 - 2;
    const int W = 2*TM2 + 4;  // 132
    for (int idx = t; idx < CC*W; idx += 256) {
        int i = idx / W, s = idx % W;
        int l = l0 + s;
        xt[i][s] = (l >= 0 && l < LL) ? g_xat[((size_t)b*CC + i)*LL + l] : 0.f;
    }
    __syncthreads();
    int o = t >> 2, qq = t & 3;             // o: output channel 0..63, qq: m quarter
    float acc[16];
    #pragma unroll
    for (int j = 0; j < 16; j++) acc[j] = 0.f;
    const float* wb = dw + (size_t)o*CC*3;
    // odd part (o<32): input = x_atten[:, :, 1::2]; even part (o>=32): [:, :, 0::2]
    int sb = 2*(qq*16) + ((o < 32) ? 1 : 0);
    for (int i = 0; i < CC; i++) {
        float w0 = __ldg(wb + i*3 + 0), w1 = __ldg(wb + i*3 + 1), w2 = __ldg(wb + i*3 + 2);
        const float* row = xt[i];
        float a0 = row[sb], a1 = row[sb+2];
        #pragma unroll
        for (int j = 0; j < 16; j++) {
            float a2 = row[sb + 4 + 2*j];
            acc[j] = fmaf(w0, a0, fmaf(w1, a1, fmaf(w2, a2, acc[j])));
            a0 = a1; a1 = a2;
        }
    }
    float s1 = 0.f, s2 = 0.f;
    size_t base = ((size_t)b*CC + o)*MM + m0 + qq*16;
    #pragma unroll
    for (int j = 0; j < 16; j++) { float v = acc[j]; g_xa[base + j] = v; s1 += v; s2 = fmaf(v, v, s2); }
    s1 += __shfl_xor_sync(0xffffffffu, s1, 1); s2 += __shfl_xor_sync(0xffffffffu, s2, 1);
    s1 += __shfl_xor_sync(0xffffffffu, s1, 2); s2 += __shfl_xor_sync(0xffffffffu, s2, 2);
    if (qq == 0) { atomicAdd(&g_s1d[o], s1); atomicAdd(&g_s2d[o], s2); }
}

// ---------------- K3: BN + ReLU + v/v1 pointwise grouped convs ----------------
__global__ void __launch_bounds__(128) k3_vconv(const float* __restrict__ vw,
                                                const float* __restrict__ v1w,
                                                const float* __restrict__ dgam,
                                                const float* __restrict__ dbet) {
    __shared__ float sc[CC], sh[CC], vws[CC*CPG], v1ws[CC*CPG];
    int t = threadIdx.x;
    if (t < CC) {
        const float invn = 1.f / (float)(BB*MM);
        float mean = g_s1d[t] * invn;
        float var  = g_s2d[t] * invn - mean*mean;
        float s = dgam[t] * rsqrtf(var + EPSV);
        sc[t] = s; sh[t] = dbet[t] - mean*s;
    }
    for (int i = t; i < CC*CPG; i += blockDim.x) { vws[i] = vw[i]; v1ws[i] = v1w[i]; }
    __syncthreads();
    int gl = blockIdx.x * blockDim.x + t;   // over B*M
    int b = gl >> 10, m = gl & (MM-1);
    size_t base = (size_t)b*CC*MM + m;
    for (int g = 0; g < GG; g++) {
        float xr[CPG];
        #pragma unroll
        for (int i = 0; i < CPG; i++) {
            int c = g*CPG + i;
            xr[i] = fmaxf(0.f, fmaf(g_xa[base + (size_t)c*MM], sc[c], sh[c]));
        }
        #pragma unroll
        for (int c = 0; c < CPG; c++) {
            float s = 0.f, s1 = 0.f;
            #pragma unroll
            for (int i = 0; i < CPG; i++) {
                s  = fmaf(vws [(g*CPG+c)*CPG+i], xr[i], s);
                s1 = fmaf(v1ws[(g*CPG+c)*CPG+i], xr[i], s1);
            }
            g_v [base + (size_t)(g*CPG+c)*MM] = s;
            g_v1[base + (size_t)(g*CPG+c)*MM] = s1;
        }
    }
}

// ---------------- K4: attention (per (b,h): softmax(qT k) v) + residual ----------------
__global__ void __launch_bounds__(256) k4_attn() {
    extern __shared__ float smem4[];
    float* kvs = smem4;            // [MM][8]
    float* vvs = smem4 + MM*EE;    // [MM][8]
    int t = threadIdx.x;
    int bh = blockIdx.y; int b = bh >> 3, h = bh & 7;
    size_t vbase = ((size_t)b*CC + h*EE)*MM;
    for (int e = 0; e < EE; e++) {
        for (int m = t; m < MM; m += 256) {
            kvs[m*EE + e] = g_v [vbase + (size_t)e*MM + m];
            vvs[m*EE + e] = g_v1[vbase + (size_t)e*MM + m];
        }
    }
    __syncthreads();
    int l = blockIdx.x * 256 + t;
    size_t qbase = ((size_t)b*CC + h*EE)*LL + l;
    const float rs = 0.35355339059327373f;   // 1/sqrt(E)
    float q[EE];
    #pragma unroll
    for (int e = 0; e < EE; e++) q[e] = g_qp[qbase + (size_t)e*LL] * rs;
    float a[EE];
    #pragma unroll
    for (int e = 0; e < EE; e++) a[e] = 0.f;
    float mx = -1e30f, sm = 0.f;
    const float4* kv4 = (const float4*)kvs;
    const float4* vv4 = (const float4*)vvs;
    #pragma unroll 4
    for (int m = 0; m < MM; m++) {
        float4 k0 = kv4[2*m], k1 = kv4[2*m+1];
        float s = q[0]*k0.x;
        s = fmaf(q[1], k0.y, s); s = fmaf(q[2], k0.z, s); s = fmaf(q[3], k0.w, s);
        s = fmaf(q[4], k1.x, s); s = fmaf(q[5], k1.y, s); s = fmaf(q[6], k1.z, s);
        s = fmaf(q[7], k1.w, s);
        float p;
        if (s > mx) {
            float corr = __expf(mx - s);
            sm *= corr;
            #pragma unroll
            for (int e = 0; e < EE; e++) a[e] *= corr;
            mx = s; p = 1.f;
        } else {
            p = __expf(s - mx);
        }
        sm += p;
        float4 v0 = vv4[2*m], v1 = vv4[2*m+1];
        a[0] = fmaf(p, v0.x, a[0]); a[1] = fmaf(p, v0.y, a[1]);
        a[2] = fmaf(p, v0.z, a[2]); a[3] = fmaf(p, v0.w, a[3]);
        a[4] = fmaf(p, v1.x, a[4]); a[5] = fmaf(p, v1.y, a[5]);
        a[6] = fmaf(p, v1.z, a[6]); a[7] = fmaf(p, v1.w, a[7]);
    }
    float inv = 1.f / sm;
    #pragma unroll
    for (int e = 0; e < EE; e++) {
        float o = a[e] * inv;
        size_t idx = qbase + (size_t)e*LL;
        g_out[idx] = o;
        g_xs[idx]  = o + g_xat[idx];
    }
}

// ---------------- K5: out conv (K=3, groups=4 over concat(xs,q_,out)) + residual + stats ----------------
#define TL5 128
__global__ void __launch_bounds__(256) k5_outconv(const float* __restrict__ ow) {
    __shared__ float xcs[48][TL5 + 2];
    int t = threadIdx.x;
    int l0 = blockIdx.x * TL5, g = blockIdx.y, b = blockIdx.z;
    const int W = TL5 + 2;
    for (int idx = t; idx < 48*W; idx += 256) {
        int j = idx / W, s = idx % W;
        int l = l0 - 1 + s;
        int u = g*48 + j;
        float val = 0.f;
        if (l >= 0 && l < LL) {
            const float* src; int ch;
            if      (u < 64)  { src = g_xs;  ch = u; }
            else if (u < 128) { src = g_qp;  ch = u - 64; }
            else              { src = g_out; ch = u - 128; }
            val = src[((size_t)b*CC + ch)*LL + l];
        }
        xcs[j][s] = val;
    }
    __syncthreads();
    int cl = t >> 4, sub = t & 15;
    int c = g*CPG + cl;
    int lbase = sub * 8;
    float acc[8];
    #pragma unroll
    for (int jj = 0; jj < 8; jj++) acc[jj] = 0.f;
    const float* wb = ow + (size_t)c*48*3;
    for (int j = 0; j < 48; j++) {
        float w0 = __ldg(wb + j*3 + 0), w1 = __ldg(wb + j*3 + 1), w2 = __ldg(wb + j*3 + 2);
        const float* row = xcs[j];
        float a0 = row[lbase], a1 = row[lbase+1];
        #pragma unroll
        for (int jj = 0; jj < 8; jj++) {
            float a2 = row[lbase + 2 + jj];
            acc[jj] = fmaf(w0, a0, fmaf(w1, a1, fmaf(w2, a2, acc[jj])));
            a0 = a1; a1 = a2;
        }
    }
    float s1 = 0.f, s2 = 0.f;
    size_t base = ((size_t)b*CC + c)*LL + l0 + lbase;
    #pragma unroll
    for (int jj = 0; jj < 8; jj++) {
        float v = acc[jj] + g_xs[base + jj];
        g_xs2[base + jj] = v;
        s1 += v; s2 = fmaf(v, v, s2);
    }
    #pragma unroll
    for (int k = 1; k < 16; k <<= 1) {
        s1 += __shfl_xor_sync(0xffffffffu, s1, k);
        s2 += __shfl_xor_sync(0xffffffffu, s2, k);
    }
    if (sub == 0) { atomicAdd(&g_s1f[c], s1); atomicAdd(&g_s2f[c], s2); }
}

// ---------------- K6: final BN + ReLU -> output ----------------
__global__ void __launch_bounds__(256) k6_final(const float* __restrict__ gam,
                                                const float* __restrict__ bet,
                                                float* __restrict__ out) {
    int idx = blockIdx.x * 256 + threadIdx.x;
    int c = (idx >> 11) & (CC-1);
    const float invn = 1.f / (float)(BB*LL);
    float mean = g_s1f[c] * invn;
    float var  = g_s2f[c] * invn - mean*mean;
    float s  = gam[c] * rsqrtf(var + EPSV);
    float shv = bet[c] - mean*s;
    out[idx] = fmaxf(0.f, fmaf(g_xs2[idx], s, shv));
}

// ---------------- launch ----------------
extern "C" void kernel_launch(void* const* d_in, const int* in_sizes, int n_in,
                              void* d_out, int out_size) {
    const float* x   = (const float*)d_in[0];
    const float* qw  = (const float*)d_in[1];
    const float* kw  = (const float*)d_in[2];
    const float* vw  = (const float*)d_in[3];
    const float* v1w = (const float*)d_in[4];
    const float* ow  = (const float*)d_in[5];
    const float* dw  = (const float*)d_in[6];
    const float* dg  = (const float*)d_in[7];
    const float* db  = (const float*)d_in[8];
    const float* gam = (const float*)d_in[9];
    const float* bet = (const float*)d_in[10];
    float* out = (float*)d_out;

    cudaFuncSetAttribute(k4_attn, cudaFuncAttributeMaxDynamicSharedMemorySize, 2*MM*EE*4);

    k0_init<<<1, 64>>>();
    k1_gate<<<(BB*LL)/128, 128>>>(x, qw, kw);
    k2_down<<<dim3(MM/TM2, BB), 256>>>(dw);
    k3_vconv<<<(BB*MM)/128, 128>>>(vw, v1w, dg, db);
    k4_attn<<<dim3(LL/256, BB*HH), 256, 2*MM*EE*4>>>();
    k5_outconv<<<dim3(LL/TL5, GG, BB), 256>>>(ow);
    k6_final<<<(BB*CC*LL)/256, 256>>>(gam, bet, out);
}

// round 2
// speedup vs baseline: 1.4085x; 1.4085x over previous
#include <cuda_runtime.h>
#include <math.h>

#define BB 8
#define CC 64
#define LL 2048
#define MM 1024
#define GG 4
#define CPG 16
#define HH 8
#define EE 8
#define EPSV 1e-5f

typedef unsigned long long ull;

// ---------------- packed f32x2 helpers ----------------
__device__ __forceinline__ ull pk2(float lo, float hi) {
    ull r;
    asm("mov.b64 %0, {%1, %2};" : "=l"(r) : "r"(__float_as_uint(lo)), "r"(__float_as_uint(hi)));
    return r;
}
__device__ __forceinline__ void upk2(ull v, float& lo, float& hi) {
    unsigned int a, b;
    asm("mov.b64 {%0, %1}, %2;" : "=r"(a), "=r"(b) : "l"(v));
    lo = __uint_as_float(a); hi = __uint_as_float(b);
}
__device__ __forceinline__ ull ffma2(ull a, ull b, ull c) {
    ull d;
    asm("fma.rn.f32x2 %0, %1, %2, %3;" : "=l"(d) : "l"(a), "l"(b), "l"(c));
    return d;
}
__device__ __forceinline__ ull fmul2(ull a, ull b) {
    ull d;
    asm("mul.rn.f32x2 %0, %1, %2;" : "=l"(d) : "l"(a), "l"(b));
    return d;
}
__device__ __forceinline__ float ex2f(float x) {
    float r;
    asm("ex2.approx.f32 %0, %1;" : "=f"(r) : "f"(x));
    return r;
}

// ---------------- scratch (device globals; no allocation allowed) ----------------
__device__ float g_xat[BB*CC*LL];   // x_atten
__device__ float g_qp [BB*CC*LL];   // q_ (k-conv of x_atten)
__device__ float g_xa [BB*CC*MM];   // down-conv output (pre-BN)
__device__ float g_v  [BB*CC*MM];   // v
__device__ float g_v1 [BB*CC*MM];   // v1
__device__ float g_out[BB*CC*LL];   // attention output
__device__ float g_xs [BB*CC*LL];   // out + x_atten
__device__ float g_xs2[BB*CC*LL];   // conv-out + xs (pre final BN)
__device__ float g_s1d[CC];         // down BN sum
__device__ float g_s2d[CC];         // down BN sumsq
__device__ float g_s1f[CC];         // final BN sum
__device__ float g_s2f[CC];         // final BN sumsq

// ---------------- K0: zero stat accumulators ----------------
__global__ void k0_init() {
    int t = threadIdx.x;
    if (t < CC) { g_s1d[t] = 0.f; g_s2d[t] = 0.f; g_s1f[t] = 0.f; g_s2f[t] = 0.f; }
}

// ---------------- K1: q conv -> sigmoid gate -> x_atten -> q_ conv ----------------
__global__ void __launch_bounds__(128) k1_gate(const float* __restrict__ x,
                                               const float* __restrict__ qw,
                                               const float* __restrict__ kw) {
    __shared__ float qws[CC*CPG], kws[CC*CPG];
    for (int i = threadIdx.x; i < CC*CPG; i += blockDim.x) { qws[i] = qw[i]; kws[i] = kw[i]; }
    __syncthreads();
    int gl = blockIdx.x * blockDim.x + threadIdx.x;   // over B*L
    int b = gl >> 11, l = gl & (LL-1);
    size_t base = (size_t)b*CC*LL + l;
    for (int g = 0; g < GG; g++) {
        float xv[CPG], xa[CPG];
        #pragma unroll
        for (int i = 0; i < CPG; i++) xv[i] = x[base + (size_t)(g*CPG+i)*LL];
        #pragma unroll
        for (int c = 0; c < CPG; c++) {
            float s = 0.f;
            #pragma unroll
            for (int i = 0; i < CPG; i++) s = fmaf(qws[(g*CPG+c)*CPG+i], xv[i], s);
            xa[c] = xv[c] / (1.f + __expf(-s));
        }
        #pragma unroll
        for (int i = 0; i < CPG; i++) g_xat[base + (size_t)(g*CPG+i)*LL] = xa[i];
        #pragma unroll
        for (int c = 0; c < CPG; c++) {
            float s = 0.f;
            #pragma unroll
            for (int i = 0; i < CPG; i++) s = fmaf(kws[(g*CPG+c)*CPG+i], xa[i], s);
            g_qp[base + (size_t)(g*CPG+c)*LL] = s;
        }
    }
}

// ---------------- K2: odd/even shuffle + down conv (K=3, groups=2) + BN stats ----------------
#define TM2 64
__global__ void __launch_bounds__(256) k2_down(const float* __restrict__ dw) {
    __shared__ float xt[CC][2*TM2 + 4];   // l-range [2*m0-2, 2*m0+130)
    int t = threadIdx.x;
    int m0 = blockIdx.x * TM2, b = blockIdx.y;
    int l0 = 2*m0 - 2;
    const int W = 2*TM2 + 4;  // 132
    for (int idx = t; idx < CC*W; idx += 256) {
        int i = idx / W, s = idx % W;
        int l = l0 + s;
        xt[i][s] = (l >= 0 && l < LL) ? g_xat[((size_t)b*CC + i)*LL + l] : 0.f;
    }
    __syncthreads();
    int o = t >> 2, qq = t & 3;             // o: output channel 0..63, qq: m quarter
    float acc[16];
    #pragma unroll
    for (int j = 0; j < 16; j++) acc[j] = 0.f;
    const float* wb = dw + (size_t)o*CC*3;
    int sb = 2*(qq*16) + ((o < 32) ? 1 : 0);
    for (int i = 0; i < CC; i++) {
        float w0 = __ldg(wb + i*3 + 0), w1 = __ldg(wb + i*3 + 1), w2 = __ldg(wb + i*3 + 2);
        const float* row = xt[i];
        float a0 = row[sb], a1 = row[sb+2];
        #pragma unroll
        for (int j = 0; j < 16; j++) {
            float a2 = row[sb + 4 + 2*j];
            acc[j] = fmaf(w0, a0, fmaf(w1, a1, fmaf(w2, a2, acc[j])));
            a0 = a1; a1 = a2;
        }
    }
    float s1 = 0.f, s2 = 0.f;
    size_t base = ((size_t)b*CC + o)*MM + m0 + qq*16;
    #pragma unroll
    for (int j = 0; j < 16; j++) { float v = acc[j]; g_xa[base + j] = v; s1 += v; s2 = fmaf(v, v, s2); }
    s1 += __shfl_xor_sync(0xffffffffu, s1, 1); s2 += __shfl_xor_sync(0xffffffffu, s2, 1);
    s1 += __shfl_xor_sync(0xffffffffu, s1, 2); s2 += __shfl_xor_sync(0xffffffffu, s2, 2);
    if (qq == 0) { atomicAdd(&g_s1d[o], s1); atomicAdd(&g_s2d[o], s2); }
}

// ---------------- K3: BN + ReLU + v/v1 pointwise grouped convs ----------------
__global__ void __launch_bounds__(128) k3_vconv(const float* __restrict__ vw,
                                                const float* __restrict__ v1w,
                                                const float* __restrict__ dgam,
                                                const float* __restrict__ dbet) {
    __shared__ float sc[CC], sh[CC], vws[CC*CPG], v1ws[CC*CPG];
    int t = threadIdx.x;
    if (t < CC) {
        const float invn = 1.f / (float)(BB*MM);
        float mean = g_s1d[t] * invn;
        float var  = g_s2d[t] * invn - mean*mean;
        float s = dgam[t] * rsqrtf(var + EPSV);
        sc[t] = s; sh[t] = dbet[t] - mean*s;
    }
    for (int i = t; i < CC*CPG; i += blockDim.x) { vws[i] = vw[i]; v1ws[i] = v1w[i]; }
    __syncthreads();
    int gl = blockIdx.x * blockDim.x + t;   // over B*M
    int b = gl >> 10, m = gl & (MM-1);
    size_t base = (size_t)b*CC*MM + m;
    for (int g = 0; g < GG; g++) {
        float xr[CPG];
        #pragma unroll
        for (int i = 0; i < CPG; i++) {
            int c = g*CPG + i;
            xr[i] = fmaxf(0.f, fmaf(g_xa[base + (size_t)c*MM], sc[c], sh[c]));
        }
        #pragma unroll
        for (int c = 0; c < CPG; c++) {
            float s = 0.f, s1 = 0.f;
            #pragma unroll
            for (int i = 0; i < CPG; i++) {
                s  = fmaf(vws [(g*CPG+c)*CPG+i], xr[i], s);
                s1 = fmaf(v1ws[(g*CPG+c)*CPG+i], xr[i], s1);
            }
            g_v [base + (size_t)(g*CPG+c)*MM] = s;
            g_v1[base + (size_t)(g*CPG+c)*MM] = s1;
        }
    }
}

// ---------------- K4: attention with packed f32x2, no-max softmax ----------------
// smem: K duplicated (k,k) rows of 20 floats (80B, padded), then V plain rows of 12 floats (48B).
#define KD_STRIDE 20
#define VS_STRIDE 12
#define KD_FLOATS (MM*KD_STRIDE)              // 20480
#define K4_SMEM ((KD_FLOATS + MM*VS_STRIDE)*4) // 131072 bytes

__global__ void __launch_bounds__(512) k4_attn() {
    extern __shared__ float sm4[];
    float* ksm = sm4;                 // [MM][20] (8 dup-pairs used)
    float* vsm = sm4 + KD_FLOATS;     // [MM][12] (8 used)
    int t = threadIdx.x;
    int bh = blockIdx.y; int b = bh >> 3, h = bh & 7;
    size_t vbase = ((size_t)b*CC + h*EE)*MM;
    const float SCL = 0.35355339059327373f * 1.4426950408889634f;  // 1/sqrt(E) * log2(e)
    // fill smem: K scaled+duplicated, V plain
    for (int m = t; m < MM; m += 512) {
        float kv[EE], vv[EE];
        #pragma unroll
        for (int e = 0; e < EE; e++) {
            kv[e] = g_v [vbase + (size_t)e*MM + m] * SCL;
            vv[e] = g_v1[vbase + (size_t)e*MM + m];
        }
        float* kr = ksm + m*KD_STRIDE;
        ((float4*)kr)[0] = make_float4(kv[0], kv[0], kv[1], kv[1]);
        ((float4*)kr)[1] = make_float4(kv[2], kv[2], kv[3], kv[3]);
        ((float4*)kr)[2] = make_float4(kv[4], kv[4], kv[5], kv[5]);
        ((float4*)kr)[3] = make_float4(kv[6], kv[6], kv[7], kv[7]);
        float* vr = vsm + m*VS_STRIDE;
        ((float4*)vr)[0] = make_float4(vv[0], vv[1], vv[2], vv[3]);
        ((float4*)vr)[1] = make_float4(vv[4], vv[5], vv[6], vv[7]);
    }
    __syncthreads();

    int l0 = blockIdx.x * 1024 + t;        // second l is l0+512
    size_t qb = ((size_t)b*CC + h*EE)*LL + l0;
    ull q01[EE];
    #pragma unroll
    for (int e = 0; e < EE; e++)
        q01[e] = pk2(g_qp[qb + (size_t)e*LL], g_qp[qb + 512 + (size_t)e*LL]);

    ull a0[4] = {0ull, 0ull, 0ull, 0ull};  // l0: e-pairs
    ull a1[4] = {0ull, 0ull, 0ull, 0ull};  // l1: e-pairs
    float sm0 = 0.f, sm1 = 0.f;

    #pragma unroll 2
    for (int m = 0; m < MM; m++) {
        const ulonglong2* kr = (const ulonglong2*)(ksm + m*KD_STRIDE);
        ulonglong2 kA = kr[0], kB = kr[1], kC = kr[2], kD = kr[3];
        ull s01 = fmul2(q01[0], kA.x);
        s01 = ffma2(q01[1], kA.y, s01);
        s01 = ffma2(q01[2], kB.x, s01);
        s01 = ffma2(q01[3], kB.y, s01);
        s01 = ffma2(q01[4], kC.x, s01);
        s01 = ffma2(q01[5], kC.y, s01);
        s01 = ffma2(q01[6], kD.x, s01);
        s01 = ffma2(q01[7], kD.y, s01);
        float s0, s1; upk2(s01, s0, s1);
        float p0 = ex2f(s0), p1 = ex2f(s1);
        sm0 += p0; sm1 += p1;
        ull pd0 = pk2(p0, p0), pd1 = pk2(p1, p1);
        const ulonglong2* vr = (const ulonglong2*)(vsm + m*VS_STRIDE);
        ulonglong2 vA = vr[0], vB = vr[1];
        a0[0] = ffma2(pd0, vA.x, a0[0]); a0[1] = ffma2(pd0, vA.y, a0[1]);
        a0[2] = ffma2(pd0, vB.x, a0[2]); a0[3] = ffma2(pd0, vB.y, a0[3]);
        a1[0] = ffma2(pd1, vA.x, a1[0]); a1[1] = ffma2(pd1, vA.y, a1[1]);
        a1[2] = ffma2(pd1, vB.x, a1[2]); a1[3] = ffma2(pd1, vB.y, a1[3]);
    }

    float i0 = 1.f / sm0, i1 = 1.f / sm1;
    #pragma unroll
    for (int j = 0; j < 4; j++) {
        float xa, xb; upk2(a0[j], xa, xb);
        float ya, yb; upk2(a1[j], ya, yb);
        size_t iA = qb + (size_t)(2*j)*LL;       // l0, e=2j
        size_t iB = iA + LL;                     // l0, e=2j+1
        float oA = xa * i0, oB = xb * i0;
        g_out[iA] = oA; g_xs[iA] = oA + g_xat[iA];
        g_out[iB] = oB; g_xs[iB] = oB + g_xat[iB];
        size_t iC = iA + 512;                    // l1, e=2j
        size_t iD = iC + LL;
        float oC = ya * i1, oD = yb * i1;
        g_out[iC] = oC; g_xs[iC] = oC + g_xat[iC];
        g_out[iD] = oD; g_xs[iD] = oD + g_xat[iD];
    }
}

// ---------------- K5: out conv (K=3, groups=4 over concat(xs,q_,out)) + residual + stats ----------------
#define TL5 128
__global__ void __launch_bounds__(256) k5_outconv(const float* __restrict__ ow) {
    __shared__ float xcs[48][TL5 + 2];
    int t = threadIdx.x;
    int l0 = blockIdx.x * TL5, g = blockIdx.y, b = blockIdx.z;
    const int W = TL5 + 2;
    for (int idx = t; idx < 48*W; idx += 256) {
        int j = idx / W, s = idx % W;
        int l = l0 - 1 + s;
        int u = g*48 + j;
        float val = 0.f;
        if (l >= 0 && l < LL) {
            const float* src; int ch;
            if      (u < 64)  { src = g_xs;  ch = u; }
            else if (u < 128) { src = g_qp;  ch = u - 64; }
            else              { src = g_out; ch = u - 128; }
            val = src[((size_t)b*CC + ch)*LL + l];
        }
        xcs[j][s] = val;
    }
    __syncthreads();
    int cl = t >> 4, sub = t & 15;
    int c = g*CPG + cl;
    int lbase = sub * 8;
    float acc[8];
    #pragma unroll
    for (int jj = 0; jj < 8; jj++) acc[jj] = 0.f;
    const float* wb = ow + (size_t)c*48*3;
    for (int j = 0; j < 48; j++) {
        float w0 = __ldg(wb + j*3 + 0), w1 = __ldg(wb + j*3 + 1), w2 = __ldg(wb + j*3 + 2);
        const float* row = xcs[j];
        float a0 = row[lbase], a1 = row[lbase+1];
        #pragma unroll
        for (int jj = 0; jj < 8; jj++) {
            float a2 = row[lbase + 2 + jj];
            acc[jj] = fmaf(w0, a0, fmaf(w1, a1, fmaf(w2, a2, acc[jj])));
            a0 = a1; a1 = a2;
        }
    }
    float s1 = 0.f, s2 = 0.f;
    size_t base = ((size_t)b*CC + c)*LL + l0 + lbase;
    #pragma unroll
    for (int jj = 0; jj < 8; jj++) {
        float v = acc[jj] + g_xs[base + jj];
        g_xs2[base + jj] = v;
        s1 += v; s2 = fmaf(v, v, s2);
    }
    #pragma unroll
    for (int k = 1; k < 16; k <<= 1) {
        s1 += __shfl_xor_sync(0xffffffffu, s1, k);
        s2 += __shfl_xor_sync(0xffffffffu, s2, k);
    }
    if (sub == 0) { atomicAdd(&g_s1f[c], s1); atomicAdd(&g_s2f[c], s2); }
}

// ---------------- K6: final BN + ReLU -> output ----------------
__global__ void __launch_bounds__(256) k6_final(const float* __restrict__ gam,
                                                const float* __restrict__ bet,
                                                float* __restrict__ out) {
    int idx = blockIdx.x * 256 + threadIdx.x;
    int c = (idx >> 11) & (CC-1);
    const float invn = 1.f / (float)(BB*LL);
    float mean = g_s1f[c] * invn;
    float var  = g_s2f[c] * invn - mean*mean;
    float s  = gam[c] * rsqrtf(var + EPSV);
    float shv = bet[c] - mean*s;
    out[idx] = fmaxf(0.f, fmaf(g_xs2[idx], s, shv));
}

// ---------------- launch ----------------
extern "C" void kernel_launch(void* const* d_in, const int* in_sizes, int n_in,
                              void* d_out, int out_size) {
    const float* x   = (const float*)d_in[0];
    const float* qw  = (const float*)d_in[1];
    const float* kw  = (const float*)d_in[2];
    const float* vw  = (const float*)d_in[3];
    const float* v1w = (const float*)d_in[4];
    const float* ow  = (const float*)d_in[5];
    const float* dw  = (const float*)d_in[6];
    const float* dg  = (const float*)d_in[7];
    const float* db  = (const float*)d_in[8];
    const float* gam = (const float*)d_in[9];
    const float* bet = (const float*)d_in[10];
    float* out = (float*)d_out;

    static int configured = 0;
    if (!configured) {
        cudaFuncSetAttribute(k4_attn, cudaFuncAttributeMaxDynamicSharedMemorySize, K4_SMEM);
        configured = 1;
    }

    k0_init<<<1, 64>>>();
    k1_gate<<<(BB*LL)/128, 128>>>(x, qw, kw);
    k2_down<<<dim3(MM/TM2, BB), 256>>>(dw);
    k3_vconv<<<(BB*MM)/128, 128>>>(vw, v1w, dg, db);
    k4_attn<<<dim3(LL/1024, BB*HH), 512, K4_SMEM>>>();
    k5_outconv<<<dim3(LL/TL5, GG, BB), 256>>>(ow);
    k6_final<<<(BB*CC*LL)/256, 256>>>(gam, bet, out);
}

// round 3
// speedup vs baseline: 1.4761x; 1.0480x over previous
#include <cuda_runtime.h>
#include <math.h>

#define BB 8
#define CC 64
#define LL 2048
#define MM 1024
#define GG 4
#define CPG 16
#define HH 8
#define EE 8
#define EPSV 1e-5f

typedef unsigned long long ull;

// ---------------- packed f32x2 helpers ----------------
__device__ __forceinline__ ull pk2(float lo, float hi) {
    ull r;
    asm("mov.b64 %0, {%1, %2};" : "=l"(r) : "r"(__float_as_uint(lo)), "r"(__float_as_uint(hi)));
    return r;
}
__device__ __forceinline__ void upk2(ull v, float& lo, float& hi) {
    unsigned int a, b;
    asm("mov.b64 {%0, %1}, %2;" : "=r"(a), "=r"(b) : "l"(v));
    lo = __uint_as_float(a); hi = __uint_as_float(b);
}
__device__ __forceinline__ ull ffma2(ull a, ull b, ull c) {
    ull d;
    asm("fma.rn.f32x2 %0, %1, %2, %3;" : "=l"(d) : "l"(a), "l"(b), "l"(c));
    return d;
}
__device__ __forceinline__ ull fmul2(ull a, ull b) {
    ull d;
    asm("mul.rn.f32x2 %0, %1, %2;" : "=l"(d) : "l"(a), "l"(b));
    return d;
}
__device__ __forceinline__ float ex2f(float x) {
    float r;
    asm("ex2.approx.f32 %0, %1;" : "=f"(r) : "f"(x));
    return r;
}

// ---------------- scratch ----------------
__device__ float g_xat[BB*CC*LL];
__device__ float g_qp [BB*CC*LL];
__device__ float g_xa [BB*CC*MM];
__device__ float g_v  [BB*CC*MM];
__device__ float g_v1 [BB*CC*MM];
__device__ float g_out[BB*CC*LL];
__device__ float g_xs [BB*CC*LL];
__device__ float g_xs2[BB*CC*LL];
__device__ float g_s1d[CC];
__device__ float g_s2d[CC];
__device__ float g_s1f[CC];
__device__ float g_s2f[CC];

// ---------------- K1: q conv -> sigmoid gate -> x_atten -> q_ conv (per-group blocks) ----------------
__global__ void __launch_bounds__(256) k1_gate(const float* __restrict__ x,
                                               const float* __restrict__ qw,
                                               const float* __restrict__ kw) {
    __shared__ float qws[CPG*CPG], kws[CPG*CPG];
    int t = threadIdx.x;
    int g = blockIdx.y;
    // fold in stat zeroing (runs once; consumed only by later kernels)
    if (blockIdx.x == 0 && g == 0 && t < CC) {
        g_s1d[t] = 0.f; g_s2d[t] = 0.f; g_s1f[t] = 0.f; g_s2f[t] = 0.f;
    }
    if (t < CPG*CPG) {
        qws[t] = qw[(size_t)g*CPG*CPG + t];
        kws[t] = kw[(size_t)g*CPG*CPG + t];
    }
    __syncthreads();
    int gl = blockIdx.x * 256 + t;   // over B*L
    int b = gl >> 11, l = gl & (LL-1);
    size_t base = (size_t)b*CC*LL + l + (size_t)g*CPG*LL;
    float xv[CPG], xa[CPG];
    #pragma unroll
    for (int i = 0; i < CPG; i++) xv[i] = x[base + (size_t)i*LL];
    #pragma unroll
    for (int c = 0; c < CPG; c++) {
        float s = 0.f;
        #pragma unroll
        for (int i = 0; i < CPG; i++) s = fmaf(qws[c*CPG+i], xv[i], s);
        xa[c] = xv[c] / (1.f + __expf(-s));
    }
    #pragma unroll
    for (int i = 0; i < CPG; i++) g_xat[base + (size_t)i*LL] = xa[i];
    #pragma unroll
    for (int c = 0; c < CPG; c++) {
        float s = 0.f;
        #pragma unroll
        for (int i = 0; i < CPG; i++) s = fmaf(kws[c*CPG+i], xa[i], s);
        g_qp[base + (size_t)c*LL] = s;
    }
}

// ---------------- K2: odd/even shuffle + down conv (K=3, groups=2) + BN stats ----------------
#define TM2 32
__global__ void __launch_bounds__(256) k2_down(const float* __restrict__ dw) {
    __shared__ float xt[CC][2*TM2 + 4];   // W = 68
    int t = threadIdx.x;
    int m0 = blockIdx.x * TM2, b = blockIdx.y;
    int l0 = 2*m0 - 2;
    const int W = 2*TM2 + 4;
    for (int idx = t; idx < CC*W; idx += 256) {
        int i = idx / W, s = idx % W;
        int l = l0 + s;
        xt[i][s] = (l >= 0 && l < LL) ? g_xat[((size_t)b*CC + i)*LL + l] : 0.f;
    }
    __syncthreads();
    int o = t >> 2, qq = t & 3;             // o: out channel, qq: m-eighth (8 m's each)
    float acc[8];
    #pragma unroll
    for (int j = 0; j < 8; j++) acc[j] = 0.f;
    const float* wb = dw + (size_t)o*CC*3;
    int sb = 2*(qq*8) + ((o < 32) ? 1 : 0);
    for (int i = 0; i < CC; i++) {
        float w0 = __ldg(wb + i*3 + 0), w1 = __ldg(wb + i*3 + 1), w2 = __ldg(wb + i*3 + 2);
        const float* row = xt[i];
        float a0 = row[sb], a1 = row[sb+2];
        #pragma unroll
        for (int j = 0; j < 8; j++) {
            float a2 = row[sb + 4 + 2*j];
            acc[j] = fmaf(w0, a0, fmaf(w1, a1, fmaf(w2, a2, acc[j])));
            a0 = a1; a1 = a2;
        }
    }
    float s1 = 0.f, s2 = 0.f;
    size_t base = ((size_t)b*CC + o)*MM + m0 + qq*8;
    #pragma unroll
    for (int j = 0; j < 8; j++) { float v = acc[j]; g_xa[base + j] = v; s1 += v; s2 = fmaf(v, v, s2); }
    s1 += __shfl_xor_sync(0xffffffffu, s1, 1); s2 += __shfl_xor_sync(0xffffffffu, s2, 1);
    s1 += __shfl_xor_sync(0xffffffffu, s1, 2); s2 += __shfl_xor_sync(0xffffffffu, s2, 2);
    if (qq == 0) { atomicAdd(&g_s1d[o], s1); atomicAdd(&g_s2d[o], s2); }
}

// ---------------- K3: BN + ReLU + v/v1 pointwise grouped convs (per-group blocks) ----------------
__global__ void __launch_bounds__(256) k3_vconv(const float* __restrict__ vw,
                                                const float* __restrict__ v1w,
                                                const float* __restrict__ dgam,
                                                const float* __restrict__ dbet) {
    __shared__ float sc[CPG], sh[CPG], vws[CPG*CPG], v1ws[CPG*CPG];
    int t = threadIdx.x;
    int g = blockIdx.y;
    if (t < CPG) {
        int c = g*CPG + t;
        const float invn = 1.f / (float)(BB*MM);
        float mean = g_s1d[c] * invn;
        float var  = g_s2d[c] * invn - mean*mean;
        float s = dgam[c] * rsqrtf(var + EPSV);
        sc[t] = s; sh[t] = dbet[c] - mean*s;
    }
    if (t < CPG*CPG) {
        vws[t]  = vw [(size_t)g*CPG*CPG + t];
        v1ws[t] = v1w[(size_t)g*CPG*CPG + t];
    }
    __syncthreads();
    int gl = blockIdx.x * 256 + t;   // over B*M
    int b = gl >> 10, m = gl & (MM-1);
    size_t base = (size_t)b*CC*MM + m + (size_t)g*CPG*MM;
    float xr[CPG];
    #pragma unroll
    for (int i = 0; i < CPG; i++)
        xr[i] = fmaxf(0.f, fmaf(g_xa[base + (size_t)i*MM], sc[i], sh[i]));
    #pragma unroll
    for (int c = 0; c < CPG; c++) {
        float s = 0.f, s1 = 0.f;
        #pragma unroll
        for (int i = 0; i < CPG; i++) {
            s  = fmaf(vws [c*CPG+i], xr[i], s);
            s1 = fmaf(v1ws[c*CPG+i], xr[i], s1);
        }
        g_v [base + (size_t)c*MM] = s;
        g_v1[base + (size_t)c*MM] = s1;
    }
}

// ---------------- K4: attention, packed f32x2, 4 l's per thread ----------------
#define KD_STRIDE 20
#define VS_STRIDE 12
#define KD_FLOATS (MM*KD_STRIDE)
#define K4_SMEM ((KD_FLOATS + MM*VS_STRIDE)*4)   // 131072 bytes

__global__ void __launch_bounds__(256) k4_attn() {
    extern __shared__ float sm4[];
    float* ksm = sm4;                 // [MM][20] (8 dup-pairs used)
    float* vsm = sm4 + KD_FLOATS;     // [MM][12] (8 used)
    int t = threadIdx.x;
    int bh = blockIdx.y; int b = bh >> 3, h = bh & 7;
    size_t vbase = ((size_t)b*CC + h*EE)*MM;
    const float SCL = 0.35355339059327373f * 1.4426950408889634f;  // 1/sqrt(E)*log2(e)
    for (int m = t; m < MM; m += 256) {
        float kv[EE], vv[EE];
        #pragma unroll
        for (int e = 0; e < EE; e++) {
            kv[e] = g_v [vbase + (size_t)e*MM + m] * SCL;
            vv[e] = g_v1[vbase + (size_t)e*MM + m];
        }
        float* kr = ksm + m*KD_STRIDE;
        ((float4*)kr)[0] = make_float4(kv[0], kv[0], kv[1], kv[1]);
        ((float4*)kr)[1] = make_float4(kv[2], kv[2], kv[3], kv[3]);
        ((float4*)kr)[2] = make_float4(kv[4], kv[4], kv[5], kv[5]);
        ((float4*)kr)[3] = make_float4(kv[6], kv[6], kv[7], kv[7]);
        float* vr = vsm + m*VS_STRIDE;
        ((float4*)vr)[0] = make_float4(vv[0], vv[1], vv[2], vv[3]);
        ((float4*)vr)[1] = make_float4(vv[4], vv[5], vv[6], vv[7]);
    }
    __syncthreads();

    int lb = blockIdx.x * 1024 + t;   // lA=lb, lB=lb+256, lC=lb+512, lD=lb+768
    size_t qb = ((size_t)b*CC + h*EE)*LL + lb;
    ull q01[EE], q23[EE];
    #pragma unroll
    for (int e = 0; e < EE; e++) {
        size_t r = qb + (size_t)e*LL;
        q01[e] = pk2(g_qp[r],       g_qp[r + 256]);
        q23[e] = pk2(g_qp[r + 512], g_qp[r + 768]);
    }
    ull aA[4] = {0,0,0,0}, aB[4] = {0,0,0,0}, aC[4] = {0,0,0,0}, aD[4] = {0,0,0,0};
    float smA = 0.f, smB = 0.f, smC = 0.f, smD = 0.f;

    #pragma unroll 2
    for (int m = 0; m < MM; m++) {
        const ulonglong2* kr = (const ulonglong2*)(ksm + m*KD_STRIDE);
        ulonglong2 kA = kr[0], kB = kr[1], kC = kr[2], kD = kr[3];
        ull s01 = fmul2(q01[0], kA.x);
        ull s23 = fmul2(q23[0], kA.x);
        s01 = ffma2(q01[1], kA.y, s01);  s23 = ffma2(q23[1], kA.y, s23);
        s01 = ffma2(q01[2], kB.x, s01);  s23 = ffma2(q23[2], kB.x, s23);
        s01 = ffma2(q01[3], kB.y, s01);  s23 = ffma2(q23[3], kB.y, s23);
        s01 = ffma2(q01[4], kC.x, s01);  s23 = ffma2(q23[4], kC.x, s23);
        s01 = ffma2(q01[5], kC.y, s01);  s23 = ffma2(q23[5], kC.y, s23);
        s01 = ffma2(q01[6], kD.x, s01);  s23 = ffma2(q23[6], kD.x, s23);
        s01 = ffma2(q01[7], kD.y, s01);  s23 = ffma2(q23[7], kD.y, s23);
        float s0, s1, s2, s3;
        upk2(s01, s0, s1); upk2(s23, s2, s3);
        float p0 = ex2f(s0), p1 = ex2f(s1), p2 = ex2f(s2), p3 = ex2f(s3);
        smA += p0; smB += p1; smC += p2; smD += p3;
        ull pA = pk2(p0, p0), pB = pk2(p1, p1), pC = pk2(p2, p2), pD = pk2(p3, p3);
        const ulonglong2* vr = (const ulonglong2*)(vsm + m*VS_STRIDE);
        ulonglong2 vA = vr[0], vB = vr[1];
        aA[0] = ffma2(pA, vA.x, aA[0]); aA[1] = ffma2(pA, vA.y, aA[1]);
        aA[2] = ffma2(pA, vB.x, aA[2]); aA[3] = ffma2(pA, vB.y, aA[3]);
        aB[0] = ffma2(pB, vA.x, aB[0]); aB[1] = ffma2(pB, vA.y, aB[1]);
        aB[2] = ffma2(pB, vB.x, aB[2]); aB[3] = ffma2(pB, vB.y, aB[3]);
        aC[0] = ffma2(pC, vA.x, aC[0]); aC[1] = ffma2(pC, vA.y, aC[1]);
        aC[2] = ffma2(pC, vB.x, aC[2]); aC[3] = ffma2(pC, vB.y, aC[3]);
        aD[0] = ffma2(pD, vA.x, aD[0]); aD[1] = ffma2(pD, vA.y, aD[1]);
        aD[2] = ffma2(pD, vB.x, aD[2]); aD[3] = ffma2(pD, vB.y, aD[3]);
    }

    float iA = 1.f / smA, iB = 1.f / smB, iC = 1.f / smC, iD = 1.f / smD;
    #pragma unroll
    for (int j = 0; j < 4; j++) {
        float x0, x1, y0, y1, z0, z1, w0, w1;
        upk2(aA[j], x0, x1); upk2(aB[j], y0, y1);
        upk2(aC[j], z0, z1); upk2(aD[j], w0, w1);
        size_t r0 = qb + (size_t)(2*j)*LL;       // e = 2j
        size_t r1 = r0 + LL;                     // e = 2j+1
        float v;
        v = x0*iA; g_out[r0      ] = v; g_xs[r0      ] = v + g_xat[r0      ];
        v = x1*iA; g_out[r1      ] = v; g_xs[r1      ] = v + g_xat[r1      ];
        v = y0*iB; g_out[r0 + 256] = v; g_xs[r0 + 256] = v + g_xat[r0 + 256];
        v = y1*iB; g_out[r1 + 256] = v; g_xs[r1 + 256] = v + g_xat[r1 + 256];
        v = z0*iC; g_out[r0 + 512] = v; g_xs[r0 + 512] = v + g_xat[r0 + 512];
        v = z1*iC; g_out[r1 + 512] = v; g_xs[r1 + 512] = v + g_xat[r1 + 512];
        v = w0*iD; g_out[r0 + 768] = v; g_xs[r0 + 768] = v + g_xat[r0 + 768];
        v = w1*iD; g_out[r1 + 768] = v; g_xs[r1 + 768] = v + g_xat[r1 + 768];
    }
}

// ---------------- K5: out conv (K=3, groups=4 over concat(xs,q_,out)) + residual + stats ----------------
#define TL5 128
__global__ void __launch_bounds__(256) k5_outconv(const float* __restrict__ ow) {
    __shared__ float xcs[48][TL5 + 2];
    int t = threadIdx.x;
    int l0 = blockIdx.x * TL5, g = blockIdx.y, b = blockIdx.z;
    const int W = TL5 + 2;
    for (int idx = t; idx < 48*W; idx += 256) {
        int j = idx / W, s = idx % W;
        int l = l0 - 1 + s;
        int u = g*48 + j;
        float val = 0.f;
        if (l >= 0 && l < LL) {
            const float* src; int ch;
            if      (u < 64)  { src = g_xs;  ch = u; }
            else if (u < 128) { src = g_qp;  ch = u - 64; }
            else              { src = g_out; ch = u - 128; }
            val = src[((size_t)b*CC + ch)*LL + l];
        }
        xcs[j][s] = val;
    }
    __syncthreads();
    int cl = t >> 4, sub = t & 15;
    int c = g*CPG + cl;
    int lbase = sub * 8;
    float acc[8];
    #pragma unroll
    for (int jj = 0; jj < 8; jj++) acc[jj] = 0.f;
    const float* wb = ow + (size_t)c*48*3;
    for (int j = 0; j < 48; j++) {
        float w0 = __ldg(wb + j*3 + 0), w1 = __ldg(wb + j*3 + 1), w2 = __ldg(wb + j*3 + 2);
        const float* row = xcs[j];
        float a0 = row[lbase], a1 = row[lbase+1];
        #pragma unroll
        for (int jj = 0; jj < 8; jj++) {
            float a2 = row[lbase + 2 + jj];
            acc[jj] = fmaf(w0, a0, fmaf(w1, a1, fmaf(w2, a2, acc[jj])));
            a0 = a1; a1 = a2;
        }
    }
    float s1 = 0.f, s2 = 0.f;
    size_t base = ((size_t)b*CC + c)*LL + l0 + lbase;
    #pragma unroll
    for (int jj = 0; jj < 8; jj++) {
        float v = acc[jj] + g_xs[base + jj];
        g_xs2[base + jj] = v;
        s1 += v; s2 = fmaf(v, v, s2);
    }
    #pragma unroll
    for (int k = 1; k < 16; k <<= 1) {
        s1 += __shfl_xor_sync(0xffffffffu, s1, k);
        s2 += __shfl_xor_sync(0xffffffffu, s2, k);
    }
    if (sub == 0) { atomicAdd(&g_s1f[c], s1); atomicAdd(&g_s2f[c], s2); }
}

// ---------------- K6: final BN + ReLU -> output ----------------
__global__ void __launch_bounds__(256) k6_final(const float* __restrict__ gam,
                                                const float* __restrict__ bet,
                                                float* __restrict__ out) {
    int idx = blockIdx.x * 256 + threadIdx.x;
    int c = (idx >> 11) & (CC-1);
    const float invn = 1.f / (float)(BB*LL);
    float mean = g_s1f[c] * invn;
    float var  = g_s2f[c] * invn - mean*mean;
    float s  = gam[c] * rsqrtf(var + EPSV);
    float shv = bet[c] - mean*s;
    out[idx] = fmaxf(0.f, fmaf(g_xs2[idx], s, shv));
}

// ---------------- launch ----------------
extern "C" void kernel_launch(void* const* d_in, const int* in_sizes, int n_in,
                              void* d_out, int out_size) {
    const float* x   = (const float*)d_in[0];
    const float* qw  = (const float*)d_in[1];
    const float* kw  = (const float*)d_in[2];
    const float* vw  = (const float*)d_in[3];
    const float* v1w = (const float*)d_in[4];
    const float* ow  = (const float*)d_in[5];
    const float* dw  = (const float*)d_in[6];
    const float* dg  = (const float*)d_in[7];
    const float* db  = (const float*)d_in[8];
    const float* gam = (const float*)d_in[9];
    const float* bet = (const float*)d_in[10];
    float* out = (float*)d_out;

    static int configured = 0;
    if (!configured) {
        cudaFuncSetAttribute(k4_attn, cudaFuncAttributeMaxDynamicSharedMemorySize, K4_SMEM);
        configured = 1;
    }

    k1_gate<<<dim3((BB*LL)/256, GG), 256>>>(x, qw, kw);
    k2_down<<<dim3(MM/TM2, BB), 256>>>(dw);
    k3_vconv<<<dim3((BB*MM)/256, GG), 256>>>(vw, v1w, dg, db);
    k4_attn<<<dim3(LL/1024, BB*HH), 256, K4_SMEM>>>();
    k5_outconv<<<dim3(LL/TL5, GG, BB), 256>>>(ow);
    k6_final<<<(BB*CC*LL)/256, 256>>>(gam, bet, out);
}

// round 4
// speedup vs baseline: 1.5013x; 1.0171x over previous
#include <cuda_runtime.h>
#include <math.h>

#define BB 8
#define CC 64
#define LL 2048
#define MM 1024
#define GG 4
#define CPG 16
#define HH 8
#define EE 8
#define EPSV 1e-5f

typedef unsigned long long ull;

// ---------------- packed f32x2 helpers ----------------
__device__ __forceinline__ ull pk2(float lo, float hi) {
    ull r;
    asm("mov.b64 %0, {%1, %2};" : "=l"(r) : "r"(__float_as_uint(lo)), "r"(__float_as_uint(hi)));
    return r;
}
__device__ __forceinline__ void upk2(ull v, float& lo, float& hi) {
    unsigned int a, b;
    asm("mov.b64 {%0, %1}, %2;" : "=r"(a), "=r"(b) : "l"(v));
    lo = __uint_as_float(a); hi = __uint_as_float(b);
}
__device__ __forceinline__ ull ffma2(ull a, ull b, ull c) {
    ull d;
    asm("fma.rn.f32x2 %0, %1, %2, %3;" : "=l"(d) : "l"(a), "l"(b), "l"(c));
    return d;
}
__device__ __forceinline__ ull fmul2(ull a, ull b) {
    ull d;
    asm("mul.rn.f32x2 %0, %1, %2;" : "=l"(d) : "l"(a), "l"(b));
    return d;
}
__device__ __forceinline__ float ex2f(float x) {
    float r;
    asm("ex2.approx.f32 %0, %1;" : "=f"(r) : "f"(x));
    return r;
}

// ---------------- scratch ----------------
__device__ float g_xat[BB*CC*LL];
__device__ float g_qp [BB*CC*LL];
__device__ float g_xa [BB*CC*MM];
__device__ float g_v  [BB*CC*MM];
__device__ float g_v1 [BB*CC*MM];
__device__ float g_out[BB*CC*LL];
__device__ float g_xs [BB*CC*LL];
__device__ float g_xs2[BB*CC*LL];
__device__ float g_pn [2*BB*CC*LL];   // partial numerators per split
__device__ float g_pd [2*BB*HH*LL];   // partial denominators per split
__device__ float g_s1d[CC];
__device__ float g_s2d[CC];
__device__ float g_s1f[CC];
__device__ float g_s2f[CC];

// ---------------- K1: q conv -> sigmoid gate -> x_atten -> q_ conv ----------------
__global__ void __launch_bounds__(256) k1_gate(const float* __restrict__ x,
                                               const float* __restrict__ qw,
                                               const float* __restrict__ kw) {
    __shared__ float qws[CPG*CPG], kws[CPG*CPG];
    int t = threadIdx.x;
    int g = blockIdx.y;
    if (blockIdx.x == 0 && g == 0 && t < CC) {
        g_s1d[t] = 0.f; g_s2d[t] = 0.f; g_s1f[t] = 0.f; g_s2f[t] = 0.f;
    }
    if (t < CPG*CPG) {
        qws[t] = qw[(size_t)g*CPG*CPG + t];
        kws[t] = kw[(size_t)g*CPG*CPG + t];
    }
    __syncthreads();
    int gl = blockIdx.x * 256 + t;
    int b = gl >> 11, l = gl & (LL-1);
    size_t base = (size_t)b*CC*LL + l + (size_t)g*CPG*LL;
    float xv[CPG], xa[CPG];
    #pragma unroll
    for (int i = 0; i < CPG; i++) xv[i] = x[base + (size_t)i*LL];
    #pragma unroll
    for (int c = 0; c < CPG; c++) {
        float s = 0.f;
        #pragma unroll
        for (int i = 0; i < CPG; i++) s = fmaf(qws[c*CPG+i], xv[i], s);
        xa[c] = xv[c] / (1.f + __expf(-s));
    }
    #pragma unroll
    for (int i = 0; i < CPG; i++) g_xat[base + (size_t)i*LL] = xa[i];
    #pragma unroll
    for (int c = 0; c < CPG; c++) {
        float s = 0.f;
        #pragma unroll
        for (int i = 0; i < CPG; i++) s = fmaf(kws[c*CPG+i], xa[i], s);
        g_qp[base + (size_t)c*LL] = s;
    }
}

// ---------------- K2: odd/even shuffle + down conv + BN stats ----------------
#define TM2 32
__global__ void __launch_bounds__(256) k2_down(const float* __restrict__ dw) {
    __shared__ float xt[CC][2*TM2 + 4];
    int t = threadIdx.x;
    int m0 = blockIdx.x * TM2, b = blockIdx.y;
    int l0 = 2*m0 - 2;
    const int W = 2*TM2 + 4;
    for (int idx = t; idx < CC*W; idx += 256) {
        int i = idx / W, s = idx % W;
        int l = l0 + s;
        xt[i][s] = (l >= 0 && l < LL) ? g_xat[((size_t)b*CC + i)*LL + l] : 0.f;
    }
    __syncthreads();
    int o = t >> 2, qq = t & 3;
    float acc[8];
    #pragma unroll
    for (int j = 0; j < 8; j++) acc[j] = 0.f;
    const float* wb = dw + (size_t)o*CC*3;
    int sb = 2*(qq*8) + ((o < 32) ? 1 : 0);
    for (int i = 0; i < CC; i++) {
        float w0 = __ldg(wb + i*3 + 0), w1 = __ldg(wb + i*3 + 1), w2 = __ldg(wb + i*3 + 2);
        const float* row = xt[i];
        float a0 = row[sb], a1 = row[sb+2];
        #pragma unroll
        for (int j = 0; j < 8; j++) {
            float a2 = row[sb + 4 + 2*j];
            acc[j] = fmaf(w0, a0, fmaf(w1, a1, fmaf(w2, a2, acc[j])));
            a0 = a1; a1 = a2;
        }
    }
    float s1 = 0.f, s2 = 0.f;
    size_t base = ((size_t)b*CC + o)*MM + m0 + qq*8;
    #pragma unroll
    for (int j = 0; j < 8; j++) { float v = acc[j]; g_xa[base + j] = v; s1 += v; s2 = fmaf(v, v, s2); }
    s1 += __shfl_xor_sync(0xffffffffu, s1, 1); s2 += __shfl_xor_sync(0xffffffffu, s2, 1);
    s1 += __shfl_xor_sync(0xffffffffu, s1, 2); s2 += __shfl_xor_sync(0xffffffffu, s2, 2);
    if (qq == 0) { atomicAdd(&g_s1d[o], s1); atomicAdd(&g_s2d[o], s2); }
}

// ---------------- K3: BN + ReLU + v/v1 pointwise grouped convs ----------------
__global__ void __launch_bounds__(256) k3_vconv(const float* __restrict__ vw,
                                                const float* __restrict__ v1w,
                                                const float* __restrict__ dgam,
                                                const float* __restrict__ dbet) {
    __shared__ float sc[CPG], sh[CPG], vws[CPG*CPG], v1ws[CPG*CPG];
    int t = threadIdx.x;
    int g = blockIdx.y;
    if (t < CPG) {
        int c = g*CPG + t;
        const float invn = 1.f / (float)(BB*MM);
        float mean = g_s1d[c] * invn;
        float var  = g_s2d[c] * invn - mean*mean;
        float s = dgam[c] * rsqrtf(var + EPSV);
        sc[t] = s; sh[t] = dbet[c] - mean*s;
    }
    if (t < CPG*CPG) {
        vws[t]  = vw [(size_t)g*CPG*CPG + t];
        v1ws[t] = v1w[(size_t)g*CPG*CPG + t];
    }
    __syncthreads();
    int gl = blockIdx.x * 256 + t;
    int b = gl >> 10, m = gl & (MM-1);
    size_t base = (size_t)b*CC*MM + m + (size_t)g*CPG*MM;
    float xr[CPG];
    #pragma unroll
    for (int i = 0; i < CPG; i++)
        xr[i] = fmaxf(0.f, fmaf(g_xa[base + (size_t)i*MM], sc[i], sh[i]));
    #pragma unroll
    for (int c = 0; c < CPG; c++) {
        float s = 0.f, s1 = 0.f;
        #pragma unroll
        for (int i = 0; i < CPG; i++) {
            s  = fmaf(vws [c*CPG+i], xr[i], s);
            s1 = fmaf(v1ws[c*CPG+i], xr[i], s1);
        }
        g_v [base + (size_t)c*MM] = s;
        g_v1[base + (size_t)c*MM] = s1;
    }
}

// ---------------- K4: attention, m-split across 2 blocks, partial sums ----------------
#define SPL 2
#define MSP (MM/SPL)          // 512 m's per block
#define KD_STRIDE 20
#define VS_STRIDE 12
#define KD_FLOATS (MSP*KD_STRIDE)
#define K4_SMEM ((KD_FLOATS + MSP*VS_STRIDE)*4)   // 65536 bytes

__global__ void __launch_bounds__(256) k4_attn() {
    extern __shared__ float sm4[];
    float* ksm = sm4;
    float* vsm = sm4 + KD_FLOATS;
    int t = threadIdx.x;
    int bh = blockIdx.y; int b = bh >> 3, h = bh & 7;
    int sp = blockIdx.z; int mb = sp * MSP;
    size_t vbase = ((size_t)b*CC + h*EE)*MM + mb;
    const float SCL = 0.35355339059327373f * 1.4426950408889634f;
    for (int m = t; m < MSP; m += 256) {
        float kv[EE], vv[EE];
        #pragma unroll
        for (int e = 0; e < EE; e++) {
            kv[e] = g_v [vbase + (size_t)e*MM + m] * SCL;
            vv[e] = g_v1[vbase + (size_t)e*MM + m];
        }
        float* kr = ksm + m*KD_STRIDE;
        ((float4*)kr)[0] = make_float4(kv[0], kv[0], kv[1], kv[1]);
        ((float4*)kr)[1] = make_float4(kv[2], kv[2], kv[3], kv[3]);
        ((float4*)kr)[2] = make_float4(kv[4], kv[4], kv[5], kv[5]);
        ((float4*)kr)[3] = make_float4(kv[6], kv[6], kv[7], kv[7]);
        float* vr = vsm + m*VS_STRIDE;
        ((float4*)vr)[0] = make_float4(vv[0], vv[1], vv[2], vv[3]);
        ((float4*)vr)[1] = make_float4(vv[4], vv[5], vv[6], vv[7]);
    }
    __syncthreads();

    int lb = blockIdx.x * 1024 + t;   // lA=lb, lB=+256, lC=+512, lD=+768
    size_t qb = ((size_t)b*CC + h*EE)*LL + lb;
    ull q01[EE], q23[EE];
    #pragma unroll
    for (int e = 0; e < EE; e++) {
        size_t r = qb + (size_t)e*LL;
        q01[e] = pk2(g_qp[r],       g_qp[r + 256]);
        q23[e] = pk2(g_qp[r + 512], g_qp[r + 768]);
    }
    ull aA[4] = {0,0,0,0}, aB[4] = {0,0,0,0}, aC[4] = {0,0,0,0}, aD[4] = {0,0,0,0};
    float smA = 0.f, smB = 0.f, smC = 0.f, smD = 0.f;

    #pragma unroll 2
    for (int m = 0; m < MSP; m++) {
        const ulonglong2* kr = (const ulonglong2*)(ksm + m*KD_STRIDE);
        ulonglong2 kA = kr[0], kB = kr[1], kC = kr[2], kD = kr[3];
        ull s01 = fmul2(q01[0], kA.x);
        ull s23 = fmul2(q23[0], kA.x);
        s01 = ffma2(q01[1], kA.y, s01);  s23 = ffma2(q23[1], kA.y, s23);
        s01 = ffma2(q01[2], kB.x, s01);  s23 = ffma2(q23[2], kB.x, s23);
        s01 = ffma2(q01[3], kB.y, s01);  s23 = ffma2(q23[3], kB.y, s23);
        s01 = ffma2(q01[4], kC.x, s01);  s23 = ffma2(q23[4], kC.x, s23);
        s01 = ffma2(q01[5], kC.y, s01);  s23 = ffma2(q23[5], kC.y, s23);
        s01 = ffma2(q01[6], kD.x, s01);  s23 = ffma2(q23[6], kD.x, s23);
        s01 = ffma2(q01[7], kD.y, s01);  s23 = ffma2(q23[7], kD.y, s23);
        float s0, s1, s2, s3;
        upk2(s01, s0, s1); upk2(s23, s2, s3);
        float p0 = ex2f(s0), p1 = ex2f(s1), p2 = ex2f(s2), p3 = ex2f(s3);
        smA += p0; smB += p1; smC += p2; smD += p3;
        ull pA = pk2(p0, p0), pB = pk2(p1, p1), pC = pk2(p2, p2), pD = pk2(p3, p3);
        const ulonglong2* vr = (const ulonglong2*)(vsm + m*VS_STRIDE);
        ulonglong2 vA = vr[0], vB = vr[1];
        aA[0] = ffma2(pA, vA.x, aA[0]); aA[1] = ffma2(pA, vA.y, aA[1]);
        aA[2] = ffma2(pA, vB.x, aA[2]); aA[3] = ffma2(pA, vB.y, aA[3]);
        aB[0] = ffma2(pB, vA.x, aB[0]); aB[1] = ffma2(pB, vA.y, aB[1]);
        aB[2] = ffma2(pB, vB.x, aB[2]); aB[3] = ffma2(pB, vB.y, aB[3]);
        aC[0] = ffma2(pC, vA.x, aC[0]); aC[1] = ffma2(pC, vA.y, aC[1]);
        aC[2] = ffma2(pC, vB.x, aC[2]); aC[3] = ffma2(pC, vB.y, aC[3]);
        aD[0] = ffma2(pD, vA.x, aD[0]); aD[1] = ffma2(pD, vA.y, aD[1]);
        aD[2] = ffma2(pD, vB.x, aD[2]); aD[3] = ffma2(pD, vB.y, aD[3]);
    }

    // write partial sums (no division yet)
    float* pn = g_pn + (size_t)sp*BB*CC*LL;
    float* pd = g_pd + (size_t)sp*BB*HH*LL;
    size_t di = (size_t)bh*LL + lb;
    pd[di      ] = smA;
    pd[di + 256] = smB;
    pd[di + 512] = smC;
    pd[di + 768] = smD;
    #pragma unroll
    for (int j = 0; j < 4; j++) {
        float x0, x1, y0, y1, z0, z1, w0, w1;
        upk2(aA[j], x0, x1); upk2(aB[j], y0, y1);
        upk2(aC[j], z0, z1); upk2(aD[j], w0, w1);
        size_t r0 = qb + (size_t)(2*j)*LL;
        size_t r1 = r0 + LL;
        pn[r0      ] = x0; pn[r1      ] = x1;
        pn[r0 + 256] = y0; pn[r1 + 256] = y1;
        pn[r0 + 512] = z0; pn[r1 + 512] = z1;
        pn[r0 + 768] = w0; pn[r1 + 768] = w1;
    }
}

// ---------------- K4b: combine partials -> out, xs ----------------
__global__ void __launch_bounds__(256) k4b_combine() {
    int idx = blockIdx.x * 256 + threadIdx.x;
    int l  = idx & (LL-1);
    int ce = (idx >> 11) & (CC-1);
    int b  = idx >> 17;
    size_t di = ((size_t)(b*HH + (ce >> 3)))*LL + l;
    float den = g_pd[di] + g_pd[(size_t)BB*HH*LL + di];
    float num = g_pn[idx] + g_pn[(size_t)BB*CC*LL + idx];
    float o = num * (1.f / den);
    g_out[idx] = o;
    g_xs[idx]  = o + g_xat[idx];
}

// ---------------- K5: out conv + residual + stats ----------------
#define TL5 128
__global__ void __launch_bounds__(256) k5_outconv(const float* __restrict__ ow) {
    __shared__ float xcs[48][TL5 + 2];
    int t = threadIdx.x;
    int l0 = blockIdx.x * TL5, g = blockIdx.y, b = blockIdx.z;
    const int W = TL5 + 2;
    for (int idx = t; idx < 48*W; idx += 256) {
        int j = idx / W, s = idx % W;
        int l = l0 - 1 + s;
        int u = g*48 + j;
        float val = 0.f;
        if (l >= 0 && l < LL) {
            const float* src; int ch;
            if      (u < 64)  { src = g_xs;  ch = u; }
            else if (u < 128) { src = g_qp;  ch = u - 64; }
            else              { src = g_out; ch = u - 128; }
            val = src[((size_t)b*CC + ch)*LL + l];
        }
        xcs[j][s] = val;
    }
    __syncthreads();
    int cl = t >> 4, sub = t & 15;
    int c = g*CPG + cl;
    int lbase = sub * 8;
    float acc[8];
    #pragma unroll
    for (int jj = 0; jj < 8; jj++) acc[jj] = 0.f;
    const float* wb = ow + (size_t)c*48*3;
    for (int j = 0; j < 48; j++) {
        float w0 = __ldg(wb + j*3 + 0), w1 = __ldg(wb + j*3 + 1), w2 = __ldg(wb + j*3 + 2);
        const float* row = xcs[j];
        float a0 = row[lbase], a1 = row[lbase+1];
        #pragma unroll
        for (int jj = 0; jj < 8; jj++) {
            float a2 = row[lbase + 2 + jj];
            acc[jj] = fmaf(w0, a0, fmaf(w1, a1, fmaf(w2, a2, acc[jj])));
            a0 = a1; a1 = a2;
        }
    }
    float s1 = 0.f, s2 = 0.f;
    size_t base = ((size_t)b*CC + c)*LL + l0 + lbase;
    #pragma unroll
    for (int jj = 0; jj < 8; jj++) {
        float v = acc[jj] + g_xs[base + jj];
        g_xs2[base + jj] = v;
        s1 += v; s2 = fmaf(v, v, s2);
    }
    #pragma unroll
    for (int k = 1; k < 16; k <<= 1) {
        s1 += __shfl_xor_sync(0xffffffffu, s1, k);
        s2 += __shfl_xor_sync(0xffffffffu, s2, k);
    }
    if (sub == 0) { atomicAdd(&g_s1f[c], s1); atomicAdd(&g_s2f[c], s2); }
}

// ---------------- K6: final BN + ReLU -> output ----------------
__global__ void __launch_bounds__(256) k6_final(const float* __restrict__ gam,
                                                const float* __restrict__ bet,
                                                float* __restrict__ out) {
    int idx = blockIdx.x * 256 + threadIdx.x;
    int c = (idx >> 11) & (CC-1);
    const float invn = 1.f / (float)(BB*LL);
    float mean = g_s1f[c] * invn;
    float var  = g_s2f[c] * invn - mean*mean;
    float s  = gam[c] * rsqrtf(var + EPSV);
    float shv = bet[c] - mean*s;
    out[idx] = fmaxf(0.f, fmaf(g_xs2[idx], s, shv));
}

// ---------------- launch ----------------
extern "C" void kernel_launch(void* const* d_in, const int* in_sizes, int n_in,
                              void* d_out, int out_size) {
    const float* x   = (const float*)d_in[0];
    const float* qw  = (const float*)d_in[1];
    const float* kw  = (const float*)d_in[2];
    const float* vw  = (const float*)d_in[3];
    const float* v1w = (const float*)d_in[4];
    const float* ow  = (const float*)d_in[5];
    const float* dw  = (const float*)d_in[6];
    const float* dg  = (const float*)d_in[7];
    const float* db  = (const float*)d_in[8];
    const float* gam = (const float*)d_in[9];
    const float* bet = (const float*)d_in[10];
    float* out = (float*)d_out;

    static int configured = 0;
    if (!configured) {
        cudaFuncSetAttribute(k4_attn, cudaFuncAttributeMaxDynamicSharedMemorySize, K4_SMEM);
        configured = 1;
    }

    k1_gate<<<dim3((BB*LL)/256, GG), 256>>>(x, qw, kw);
    k2_down<<<dim3(MM/TM2, BB), 256>>>(dw);
    k3_vconv<<<dim3((BB*MM)/256, GG), 256>>>(vw, v1w, dg, db);
    k4_attn<<<dim3(LL/1024, BB*HH, SPL), 256, K4_SMEM>>>();
    k4b_combine<<<(BB*CC*LL)/256, 256>>>();
    k5_outconv<<<dim3(LL/TL5, GG, BB), 256>>>(ow);
    k6_final<<<(BB*CC*LL)/256, 256>>>(gam, bet, out);
}